// round 16
// baseline (speedup 1.0000x reference)
#include <cuda_runtime.h>
#include <cuda_fp16.h>
#include <cstdint>
#include <math.h>

#define MAXN 100000
#define IN_DIM 512

// ---------------- scratch ----------------------------------------------------
__device__ __half g_bufH[MAXN * 64];   // support matrices (gathered operand, fp16)
__device__ float  g_bufF[MAXN * 64];   // spmm outputs (fp32)
__device__ int    g_rp[MAXN + 1];
__device__ float  g_stats[384];        // 3 layers x (64 sum + 64 sumsq)
__device__ unsigned g_barCount = 0;    // grid barrier (monotonic gen -> replay-safe)
__device__ unsigned g_barGen   = 0;

// ---------------- grid barrier (persistent kernel, all blocks resident) ------
__device__ __forceinline__ void grid_barrier() {
    __threadfence();
    __syncthreads();
    if (threadIdx.x == 0) {
        volatile unsigned* vgen = &g_barGen;
        unsigned gen = *vgen;
        unsigned arrived = atomicAdd(&g_barCount, 1u) + 1u;
        if (arrived == gridDim.x) {
            g_barCount = 0;
            __threadfence();
            *vgen = gen + 1u;
        } else {
            while (*vgen == gen) __nanosleep(64);
        }
    }
    __syncthreads();
    __threadfence();
}

// ---------------- packed f32x2 FMA -------------------------------------------
__device__ __forceinline__ float2 ffma2(float2 a, float2 b, float2 c) {
    unsigned long long ua = *reinterpret_cast<unsigned long long*>(&a);
    unsigned long long ub = *reinterpret_cast<unsigned long long*>(&b);
    unsigned long long uc = *reinterpret_cast<unsigned long long*>(&c);
    unsigned long long ud;
    asm("fma.rn.f32x2 %0, %1, %2, %3;" : "=l"(ud) : "l"(ua), "l"(ub), "l"(uc));
    return *reinterpret_cast<float2*>(&ud);
}

// ---------------- HMMA m16n8k16 fp16 -> fp32 ---------------------------------
__device__ __forceinline__ void mma16816(float* c, uint32_t a0, uint32_t a1,
                                         uint32_t a2, uint32_t a3,
                                         uint32_t b0, uint32_t b1) {
    asm volatile(
        "mma.sync.aligned.m16n8k16.row.col.f32.f16.f16.f32 "
        "{%0,%1,%2,%3}, {%4,%5,%6,%7}, {%8,%9}, {%0,%1,%2,%3};"
        : "+f"(c[0]), "+f"(c[1]), "+f"(c[2]), "+f"(c[3])
        : "r"(a0), "r"(a1), "r"(a2), "r"(a3), "r"(b0), "r"(b1));
}

// ---------------- GEMM1: double-buffered, K-chunk 32, single fp16 A ----------
// Block 128x64, 8 warps (4m x 2n). One __syncthreads per tile; tile t+1 global
// loads issue before MMAs on tile t (overlap DRAM latency with tensor work).
__global__ void __launch_bounds__(256, 3) gemm1_hmma(
    const float* __restrict__ A, const float* __restrict__ B,
    __half* __restrict__ C, int M,
    const int* __restrict__ erow, int E, int* __restrict__ rp) {
    __shared__ __half sA[2][128][40];   // 10.2KB each
    __shared__ __half sB[2][64][40];    // 5.1KB each (transposed [n][k])

    int tid = threadIdx.x;

    // prologue: rowptr binary searches + stats zeroing (stream-ordered, replay-safe)
    {
        int i = blockIdx.x * 256 + tid;
        if (i <= M) {
            int lo = 0, hi = E;
            while (lo < hi) { int mid = (lo + hi) >> 1; if (erow[mid] < i) lo = mid + 1; else hi = mid; }
            rp[i] = lo;
        }
        if (blockIdx.x == 0) {
            for (int k = tid; k < 384; k += 256) g_stats[k] = 0.f;
        }
    }

    int wid = tid >> 5, lane = tid & 31;
    int wm = wid & 3, wn = wid >> 2;
    int rowBase = blockIdx.x * 128;
    int r = lane >> 2;
    int cq = (lane & 3) * 2;

    // loader indices (K-chunk 32)
    int la_row = tid >> 1;               // wrong granularity; compute per-iter below
    (void)la_row;

    float acc[2][4][4];
#pragma unroll
    for (int mt = 0; mt < 2; ++mt)
#pragma unroll
        for (int nt = 0; nt < 4; ++nt)
#pragma unroll
            for (int i = 0; i < 4; ++i) acc[mt][nt][i] = 0.f;

    // tile loader: A 128x32 (4 float4/thread), B 32x64 (2 float4/thread)
    auto load_tile = [&](int kt, int b) {
#pragma unroll
        for (int i = 0; i < 4; ++i) {
            int idx = tid + i * 256;
            int row = idx >> 3, c4 = (idx & 7) * 4;   // 8 float4 per 32-col row
            int grow = rowBase + row;
            float4 v = make_float4(0.f, 0.f, 0.f, 0.f);
            if (grow < M) v = *(const float4*)(A + (size_t)grow * 512 + kt + c4);
            *(__half2*)&sA[b][row][c4]     = __floats2half2_rn(v.x, v.y);
            *(__half2*)&sA[b][row][c4 + 2] = __floats2half2_rn(v.z, v.w);
        }
#pragma unroll
        for (int i = 0; i < 2; ++i) {
            int idx = tid + i * 256;
            int k = idx >> 4, n4 = (idx & 15) * 4;    // k 0..31
            float4 v = *(const float4*)(B + (size_t)(kt + k) * 64 + n4);
            sB[b][n4 + 0][k] = __float2half_rn(v.x);
            sB[b][n4 + 1][k] = __float2half_rn(v.y);
            sB[b][n4 + 2][k] = __float2half_rn(v.z);
            sB[b][n4 + 3][k] = __float2half_rn(v.w);
        }
    };

    load_tile(0, 0);
    __syncthreads();

    for (int t = 0; t < 16; ++t) {
        int buf = t & 1;
        if (t + 1 < 16) load_tile((t + 1) * 32, buf ^ 1);   // LDGs hoist above MMAs

#pragma unroll
        for (int ks = 0; ks < 2; ++ks) {
            int c = cq + ks * 16;
            uint32_t bh[4][2];
#pragma unroll
            for (int nt = 0; nt < 4; ++nt) {
                int col = wn * 32 + nt * 8 + r;
                bh[nt][0] = *(const uint32_t*)&sB[buf][col][c];
                bh[nt][1] = *(const uint32_t*)&sB[buf][col][c + 8];
            }
#pragma unroll
            for (int mt = 0; mt < 2; ++mt) {
                int m = wm * 32 + mt * 16;
                uint32_t a0 = *(const uint32_t*)&sA[buf][m + r][c];
                uint32_t a1 = *(const uint32_t*)&sA[buf][m + r + 8][c];
                uint32_t a2 = *(const uint32_t*)&sA[buf][m + r][c + 8];
                uint32_t a3 = *(const uint32_t*)&sA[buf][m + r + 8][c + 8];
#pragma unroll
                for (int nt = 0; nt < 4; ++nt)
                    mma16816(acc[mt][nt], a0, a1, a2, a3, bh[nt][0], bh[nt][1]);
            }
        }
        __syncthreads();
    }

#pragma unroll
    for (int mt = 0; mt < 2; ++mt) {
        int row0 = rowBase + wm * 32 + mt * 16 + r;
        int row1 = row0 + 8;
#pragma unroll
        for (int nt = 0; nt < 4; ++nt) {
            int col = wn * 32 + nt * 8 + cq;
            if (row0 < M)
                *(__half2*)(C + (size_t)row0 * 64 + col) =
                    __floats2half2_rn(acc[mt][nt][0], acc[mt][nt][1]);
            if (row1 < M)
                *(__half2*)(C + (size_t)row1 * 64 + col) =
                    __floats2half2_rn(acc[mt][nt][2], acc[mt][nt][3]);
        }
    }
}

// ---------------- fp16 gather helper (FFMA2, float2 accumulators) ------------
__device__ __forceinline__ void fma_half8(float2* acc, uint4 raw, float v) {
    float2 vv = make_float2(v, v);
    float2 f0 = __half22float2(*(__half2*)&raw.x);
    float2 f1 = __half22float2(*(((__half2*)&raw.x) + 1));
    float2 f2 = __half22float2(*(__half2*)&raw.z);
    float2 f3 = __half22float2(*(((__half2*)&raw.z) + 1));
    acc[0] = ffma2(vv, f0, acc[0]);
    acc[1] = ffma2(vv, f1, acc[1]);
    acc[2] = ffma2(vv, f2, acc[2]);
    acc[3] = ffma2(vv, f3, acc[3]);
}

// ---------------- SpMM stage with optional fused stats -----------------------
template <int D, int GRP, bool STATS>
__device__ void spmm_stage(const __half* __restrict__ sup, const int* __restrict__ ecol,
                           const float* __restrict__ ev, const int* __restrict__ rp,
                           float* __restrict__ out, int n, int layer, float* sStats) {
    const int STRIDE = 32 / GRP;
    int tid = threadIdx.x, wid = tid >> 5, lane = tid & 31;
    int g = lane / GRP, sl = lane % GRP;
    if (STATS) {
        for (int i = tid; i < 8 * 2 * D; i += 256) sStats[i] = 0.f;
        __syncthreads();
    }
    float* myStats = sStats + wid * 2 * D;
    int nwarps = gridDim.x * 8;
    for (int node = blockIdx.x * 8 + wid; node < n; node += nwarps) {
        int s = rp[node], e = rp[node + 1];
        float2 acc[4];
#pragma unroll
        for (int i = 0; i < 4; ++i) acc[i] = make_float2(0.f, 0.f);
        int j = s + g;
        for (; j + STRIDE < e; j += 2 * STRIDE) {
            int   c0 = ecol[j];          float v0 = ev[j];
            int   c1 = ecol[j + STRIDE]; float v1 = ev[j + STRIDE];
            uint4 r0 = *(const uint4*)(sup + (size_t)c0 * D + sl * 8);
            uint4 r1 = *(const uint4*)(sup + (size_t)c1 * D + sl * 8);
            fma_half8(acc, r0, v0);
            fma_half8(acc, r1, v1);
        }
        if (j < e) {
            int c = ecol[j]; float v = ev[j];
            uint4 raw = *(const uint4*)(sup + (size_t)c * D + sl * 8);
            fma_half8(acc, raw, v);
        }
#pragma unroll
        for (int o = 16; o >= GRP; o >>= 1)
#pragma unroll
            for (int i = 0; i < 4; ++i) {
                acc[i].x += __shfl_down_sync(0xffffffffu, acc[i].x, o);
                acc[i].y += __shfl_down_sync(0xffffffffu, acc[i].y, o);
            }
        if (lane < GRP) {
            float* op = out + (size_t)node * D + lane * 8;
            *(float4*)op       = make_float4(acc[0].x, acc[0].y, acc[1].x, acc[1].y);
            *(float4*)(op + 4) = make_float4(acc[2].x, acc[2].y, acc[3].x, acc[3].y);
            if (STATS) {
                float* ms = myStats + lane * 8;
                float* mq = myStats + D + lane * 8;
#pragma unroll
                for (int i = 0; i < 4; ++i) {
                    float vx = acc[i].x, vy = acc[i].y;
                    ms[2 * i + 0] += vx; mq[2 * i + 0] = fmaf(vx, vx, mq[2 * i + 0]);
                    ms[2 * i + 1] += vy; mq[2 * i + 1] = fmaf(vy, vy, mq[2 * i + 1]);
                }
            }
        }
    }
    if (STATS) {
        __syncthreads();
        for (int i = tid; i < 2 * D; i += 256) {
            float s = 0.f;
#pragma unroll
            for (int w = 0; w < 8; ++w) s += sStats[w * 2 * D + i];
            int ch  = (i < D) ? i : (i - D);
            int off = (i < D) ? 0 : 64;
            atomicAdd(&g_stats[layer * 128 + off + ch], s);
        }
        __syncthreads();
    }
}

// ---------------- fused BN+ELU + small GEMM stage (shuffle broadcast) --------
template <int IN, int OUT>
__device__ void gemm_small_stage(const float* __restrict__ h, const float* __restrict__ W,
                                 const float* __restrict__ gamma, const float* __restrict__ beta,
                                 int layer, __half* __restrict__ out, int n,
                                 float* sWs, float* sc, float* sh) {
    int tid = threadIdx.x;
    for (int i = tid; i < IN * OUT; i += 256) sWs[i] = W[i];
    if (tid < IN) {
        float invn = 1.0f / (float)n;
        float mean = g_stats[layer * 128 + tid] * invn;
        float var  = g_stats[layer * 128 + 64 + tid] * invn - mean * mean;
        float k    = rsqrtf(var + 1e-5f) * gamma[tid];
        sc[tid] = k;
        sh[tid] = beta[tid] - mean * k;
    }
    __syncthreads();
    int wid = tid >> 5, lane = tid & 31;
    float scA = (lane < IN) ? sc[lane] : 0.f;
    float shA = (lane < IN) ? sh[lane] : 0.f;
    float scB = (IN == 64) ? sc[lane + 32] : 0.f;
    float shB = (IN == 64) ? sh[lane + 32] : 0.f;
    for (int node = blockIdx.x * 8 + wid; node < n; node += gridDim.x * 8) {
        const float* hr = h + (size_t)node * IN;
        float ya = 0.f, yb = 0.f;
        if (lane < IN) {
            float xv = hr[lane];
            ya = fmaf(xv, scA, shA);
            ya = ya > 0.f ? ya : (__expf(ya) - 1.0f);
        }
        if (IN == 64) {
            float xv = hr[lane + 32];
            yb = fmaf(xv, scB, shB);
            yb = yb > 0.f ? yb : (__expf(yb) - 1.0f);
        }
        float acc = 0.f;
        const int KA = (IN < 32) ? IN : 32;
#pragma unroll
        for (int k = 0; k < KA; ++k) {
            float yk = __shfl_sync(0xffffffffu, ya, k);
            acc = fmaf(yk, sWs[k * OUT + lane], acc);
        }
        if (IN == 64) {
#pragma unroll
            for (int k = 0; k < 32; ++k) {
                float yk = __shfl_sync(0xffffffffu, yb, k);
                acc = fmaf(yk, sWs[(k + 32) * OUT + lane], acc);
            }
        }
        if (lane < OUT) out[(size_t)node * OUT + lane] = __float2half_rn(acc);
    }
    __syncthreads();
}

// ---------------- THE persistent kernel: everything after gemm1 --------------
__global__ void __launch_bounds__(256, 6) fused_rest(
    __half* __restrict__ hH, float* __restrict__ hF,
    const int* __restrict__ ecol, const float* __restrict__ ev, const int* __restrict__ rp,
    const float* __restrict__ W2, const float* __restrict__ W3, const float* __restrict__ W4,
    const float* __restrict__ g1, const float* __restrict__ b1,
    const float* __restrict__ g2, const float* __restrict__ b2,
    const float* __restrict__ g3, const float* __restrict__ b3,
    float* __restrict__ out, int n) {
    __shared__ float sWs[64 * 32];     // weights OR per-warp stats (stage-disjoint)
    __shared__ float sA[64], sB2[64];

    int tid = threadIdx.x;

    // S0: spmm64 + stats0 (hH -> hF)
    spmm_stage<64, 8, true>(hH, ecol, ev, rp, hF, n, 0, sWs);
    grid_barrier();

    // S1: bn0+elu+gemm 64->32  (hF -> hH)
    gemm_small_stage<64, 32>(hF, W2, g1, b1, 0, hH, n, sWs, sA, sB2);
    grid_barrier();

    // S2: spmm32 + stats1 (hH -> hF)
    spmm_stage<32, 4, true>(hH, ecol, ev, rp, hF, n, 1, sWs);
    grid_barrier();

    // S3: bn1+elu+gemm 32->16 (hF -> hH)
    gemm_small_stage<32, 16>(hF, W3, g2, b2, 1, hH, n, sWs, sA, sB2);
    grid_barrier();

    // S4: spmm16 + stats2 (hH -> hF)
    spmm_stage<16, 2, true>(hH, ecol, ev, rp, hF, n, 2, sWs);
    grid_barrier();

    // S5: bn2+elu (hF -> hH), elementwise
    {
        float invn = 1.0f / (float)n;
        for (int i = blockIdx.x * 256 + tid; i < n * 16; i += gridDim.x * 256) {
            int ch = i & 15;
            float mean = g_stats[256 + ch] * invn;
            float var  = g_stats[256 + 64 + ch] * invn - mean * mean;
            float k = rsqrtf(var + 1e-5f) * g3[ch];
            float y = fmaf(hF[i] - mean, k, b3[ch]);
            hH[i] = __float2half_rn(y > 0.f ? y : (__expf(y) - 1.0f));
        }
    }
    grid_barrier();

    // S6: FUSED final: spmm16 -> gemm(16->40) -> log_softmax (hH -> out)
    {
        for (int i = tid; i < 16 * 40; i += 256) sWs[i] = W4[i];
        __syncthreads();
        int wid = tid >> 5, lane = tid & 31;
        int g = lane >> 1, sl = lane & 1;       // GRP=2, STRIDE=16
        int nwarps = gridDim.x * 8;
        for (int node = blockIdx.x * 8 + wid; node < n; node += nwarps) {
            int s = rp[node], e = rp[node + 1];
            float2 acc[4];
#pragma unroll
            for (int i = 0; i < 4; ++i) acc[i] = make_float2(0.f, 0.f);
            int j = s + g;
            for (; j + 16 < e; j += 32) {
                int   c0 = ecol[j];      float v0 = ev[j];
                int   c1 = ecol[j + 16]; float v1 = ev[j + 16];
                uint4 r0 = *(const uint4*)(hH + (size_t)c0 * 16 + sl * 8);
                uint4 r1 = *(const uint4*)(hH + (size_t)c1 * 16 + sl * 8);
                fma_half8(acc, r0, v0);
                fma_half8(acc, r1, v1);
            }
            if (j < e) {
                int c = ecol[j]; float v = ev[j];
                uint4 raw = *(const uint4*)(hH + (size_t)c * 16 + sl * 8);
                fma_half8(acc, raw, v);
            }
#pragma unroll
            for (int o = 16; o >= 2; o >>= 1)
#pragma unroll
                for (int i = 0; i < 4; ++i) {
                    acc[i].x += __shfl_down_sync(0xffffffffu, acc[i].x, o);
                    acc[i].y += __shfl_down_sync(0xffffffffu, acc[i].y, o);
                }
            float acc0 = 0.f, acc1 = 0.f;
#pragma unroll
            for (int k = 0; k < 16; ++k) {
                float val = (k & 1) ? acc[(k & 7) >> 1].y : acc[(k & 7) >> 1].x;
                float yk = __shfl_sync(0xffffffffu, val, k >> 3);
                acc0 = fmaf(yk, sWs[k * 40 + lane], acc0);
                if (lane < 8) acc1 = fmaf(yk, sWs[k * 40 + 32 + lane], acc1);
            }
            float a1 = (lane < 8) ? acc1 : __int_as_float(0xff800000);
            float m = fmaxf(acc0, a1);
#pragma unroll
            for (int o = 16; o; o >>= 1) m = fmaxf(m, __shfl_xor_sync(0xffffffffu, m, o));
            float ssum = expf(acc0 - m) + ((lane < 8) ? expf(acc1 - m) : 0.f);
#pragma unroll
            for (int o = 16; o; o >>= 1) ssum += __shfl_xor_sync(0xffffffffu, ssum, o);
            float lse = logf(ssum) + m;
            out[(size_t)node * 40 + lane] = acc0 - lse;
            if (lane < 8) out[(size_t)node * 40 + 32 + lane] = acc1 - lse;
        }
    }
}

// ---------------- launch ------------------------------------------------------
static inline int dg(long long t, int b) { return (int)((t + b - 1) / b); }

extern "C" void kernel_launch(void* const* d_in, const int* in_sizes, int n_in,
                              void* d_out, int out_size) {
    const float* x    = (const float*)d_in[0];
    const int*   erow = (const int*)d_in[1];
    const int*   ecol = (const int*)d_in[2];
    const float* ev   = (const float*)d_in[3];
    const float* W1   = (const float*)d_in[4];
    const float* W2   = (const float*)d_in[5];
    const float* W3   = (const float*)d_in[6];
    const float* W4   = (const float*)d_in[7];
    const float* g1   = (const float*)d_in[8];
    const float* b1   = (const float*)d_in[9];
    const float* g2   = (const float*)d_in[10];
    const float* b2   = (const float*)d_in[11];
    const float* g3   = (const float*)d_in[12];
    const float* b3   = (const float*)d_in[13];

    int n = in_sizes[0] / IN_DIM;
    int E = in_sizes[1];
    float* out = (float*)d_out;

    __half* hH; float* hF; int* rp;
    cudaGetSymbolAddress((void**)&hH, g_bufH);
    cudaGetSymbolAddress((void**)&hF, g_bufF);
    cudaGetSymbolAddress((void**)&rp, g_rp);

    const int PERS = 148 * 6;   // co-resident capacity at launch_bounds(256,6)

    int gb = dg(n, 128);
    int rb = dg(n + 1, 256);
    int grid1 = gb > rb ? gb : rb;

    gemm1_hmma<<<grid1, 256>>>(x, W1, hH, n, erow, E, rp);
    fused_rest<<<PERS, 256>>>(hH, hF, ecol, ev, rp, W2, W3, W4,
                              g1, b1, g2, b2, g3, b3, out, n);
}